// round 3
// baseline (speedup 1.0000x reference)
#include <cuda_runtime.h>
#include <math.h>
#include <stdint.h>

#define N_TOKENS 16384
#define HIDDEN   4096
#define NEXP     64
#define TOPK     8

#define BM 64
#define BK 32
#define NTH 128
#define SX 68   // smem row stride in floats (conflict-padded)

__global__ __launch_bounds__(NTH) void router_kernel(
    const float* __restrict__ x,   // [N_TOKENS, HIDDEN]
    const float* __restrict__ W,   // [NEXP, HIDDEN]
    const float* __restrict__ b,   // [NEXP]
    float* __restrict__ out)       // concat: router | weights | indices | mask
{
    __shared__ __align__(16) float smem[2 * BK * SX];
    float* xs = smem;            // [BK][SX]  xs[k][m]  (x^T tile)
    float* ws = smem + BK * SX;  // [BK][SX]  ws[k][e]  (W^T tile)

    const int tid     = threadIdx.x;
    const int block_m = blockIdx.x * BM;

    // ---- global load mapping: 8 threads cover one 32-float K-slab of a row
    const int lk = (tid & 7) * 4;   // k offset within tile: 0,4,...,28
    const int lr = tid >> 3;        // row 0..15 -> rows {lr, lr+16, lr+32, lr+48}
    const float* xptr = x + (size_t)(block_m + lr) * HIDDEN + lk;
    const float* wptr = W + (size_t)lr * HIDDEN + lk;

    // ---- compute mapping: 4 tokens x 8 experts per thread
    const int ty = tid >> 3;   // 0..15 -> tokens ty*4 .. ty*4+3
    const int tx = tid & 7;    // 0..7  -> experts tx*8 .. tx*8+7

    float acc[4][8];
#pragma unroll
    for (int i = 0; i < 4; i++)
#pragma unroll
        for (int j = 0; j < 8; j++) acc[i][j] = 0.0f;

    float4 px[4], pw[4];
#pragma unroll
    for (int j = 0; j < 4; j++) {
        px[j] = *(const float4*)(xptr + (size_t)j * 16 * HIDDEN);
        pw[j] = *(const float4*)(wptr + (size_t)j * 16 * HIDDEN);
    }

    const int NKT = HIDDEN / BK;   // 128
    for (int kt = 0; kt < NKT; ++kt) {
        __syncthreads();
        // store transposed into smem
#pragma unroll
        for (int j = 0; j < 4; j++) {
            const int m = lr + j * 16;
            xs[(lk + 0) * SX + m] = px[j].x;
            xs[(lk + 1) * SX + m] = px[j].y;
            xs[(lk + 2) * SX + m] = px[j].z;
            xs[(lk + 3) * SX + m] = px[j].w;
            ws[(lk + 0) * SX + m] = pw[j].x;
            ws[(lk + 1) * SX + m] = pw[j].y;
            ws[(lk + 2) * SX + m] = pw[j].z;
            ws[(lk + 3) * SX + m] = pw[j].w;
        }
        __syncthreads();

        // prefetch next tile while computing this one
        if (kt + 1 < NKT) {
            const float* xn = xptr + (size_t)(kt + 1) * BK;
            const float* wn = wptr + (size_t)(kt + 1) * BK;
#pragma unroll
            for (int j = 0; j < 4; j++) {
                px[j] = *(const float4*)(xn + (size_t)j * 16 * HIDDEN);
                pw[j] = *(const float4*)(wn + (size_t)j * 16 * HIDDEN);
            }
        }

#pragma unroll
        for (int kk = 0; kk < BK; ++kk) {
            const float4 a  = *(const float4*)&xs[kk * SX + ty * 4];
            const float4 w0 = *(const float4*)&ws[kk * SX + tx * 8];
            const float4 w1 = *(const float4*)&ws[kk * SX + tx * 8 + 4];
            const float av[4] = {a.x, a.y, a.z, a.w};
            const float wv[8] = {w0.x, w0.y, w0.z, w0.w, w1.x, w1.y, w1.z, w1.w};
#pragma unroll
            for (int i = 0; i < 4; i++)
#pragma unroll
                for (int j = 0; j < 8; j++)
                    acc[i][j] = fmaf(av[i], wv[j], acc[i][j]);
        }
    }

    // ---------------- epilogue ----------------
    float bias[8];
#pragma unroll
    for (int j = 0; j < 8; j++) bias[j] = __ldg(b + tx * 8 + j);

    float* outR    = out;                                        // [N,64]
    float* outWt   = out + (size_t)N_TOKENS * NEXP;              // [N,8]
    float* outIdx  = outWt + (size_t)N_TOKENS * TOPK;            // [N,8]
    float* outMask = outIdx + (size_t)N_TOKENS * TOPK;           // [64,8,N]

    __syncthreads();          // smem tiles dead; reuse as logits [BM][65]
    float* lg = smem;

#pragma unroll
    for (int i = 0; i < 4; i++) {
        const int m = ty * 4 + i;
        float v[8];
#pragma unroll
        for (int j = 0; j < 8; j++) {
            v[j] = acc[i][j] + bias[j];
            lg[m * 65 + tx * 8 + j] = v[j];
        }
        float4 r0 = make_float4(v[0], v[1], v[2], v[3]);
        float4 r1 = make_float4(v[4], v[5], v[6], v[7]);
        float* dst = outR + (size_t)(block_m + m) * NEXP + tx * 8;
        *(float4*)dst       = r0;
        *(float4*)(dst + 4) = r1;
    }
    __syncthreads();

    if (tid < BM) {
        const int m  = tid;
        const int gm = block_m + m;
        float* row = lg + m * 65;

        float mx = row[0];
#pragma unroll
        for (int e = 1; e < NEXP; e++) mx = fmaxf(mx, row[e]);

        float vals[TOPK];
        int   idxs[TOPK];
#pragma unroll
        for (int k = 0; k < TOPK; k++) {
            float best = -INFINITY;
            int   bi   = 0;
            for (int e = 0; e < NEXP; e++) {
                const float t = row[e];
                if (t > best) { best = t; bi = e; }   // strict >: first index on ties (jax)
            }
            vals[k] = best;
            idxs[k] = bi;
            row[bi] = -INFINITY;
        }

        float ex[TOPK], s = 0.0f;
#pragma unroll
        for (int k = 0; k < TOPK; k++) { ex[k] = expf(vals[k] - mx); s += ex[k]; }
        const float inv = 1.0f / s;

#pragma unroll
        for (int k = 0; k < TOPK; k++) {
            outWt[(size_t)gm * TOPK + k]  = ex[k] * inv;
            outIdx[(size_t)gm * TOPK + k] = (float)idxs[k];
            outMask[(size_t)(idxs[k] * TOPK + k) * N_TOKENS + gm] = 1.0f;
        }
    }
}

extern "C" void kernel_launch(void* const* d_in, const int* in_sizes, int n_in,
                              void* d_out, int out_size)
{
    const float* x = (const float*)d_in[0];
    const float* W = (const float*)d_in[1];
    const float* b = (const float*)d_in[2];
    float* out = (float*)d_out;

    // zero the expert_mask region (rest of out is fully overwritten)
    float* mask = out + (size_t)N_TOKENS * NEXP + 2 * (size_t)N_TOKENS * TOPK;
    cudaMemsetAsync(mask, 0, (size_t)NEXP * TOPK * N_TOKENS * sizeof(float), 0);

    router_kernel<<<N_TOKENS / BM, NTH>>>(x, W, b, out);
}

// round 7
// speedup vs baseline: 1.7725x; 1.7725x over previous
#include <cuda_runtime.h>
#include <cuda_bf16.h>
#include <math.h>
#include <stdint.h>

#define N_TOKENS 16384
#define HIDDEN   4096
#define NEXP     64
#define TOPK     8

#define BM       128          // tokens per CTA
#define TK       64           // k per tile
#define NKT      (HIDDEN/TK)  // 64 k-tiles
#define NTH      512          // 16 warps: 4 (M) x 4 (N)

#define A_TERM_BYTES (BM*TK*2)        // 16384
#define B_TERM_BYTES (NEXP*TK*2)      // 8192
#define A_STAGE      (3*A_TERM_BYTES) // 49152
#define B_STAGE      (3*B_TERM_BYTES) // 24576
#define STAGE_BYTES  (A_STAGE+B_STAGE)// 73728
#define SMEM_BYTES   (1024 + 2*STAGE_BYTES)
#define CRS          72               // C smem row stride (floats)

// pre-split, pre-swizzled W: [tile t][term s][expert row][64 k] bf16
__device__ __align__(16) unsigned char g_wb[NKT * B_STAGE];

// ---------------- helpers ----------------
__device__ __forceinline__ uint32_t smem_u32(const void* p) {
    uint32_t a;
    asm("{ .reg .u64 t; cvta.to.shared.u64 t, %1; cvt.u32.u64 %0, t; }" : "=r"(a) : "l"(p));
    return a;
}
__device__ __forceinline__ uint32_t sw128(uint32_t o) { return o ^ ((o >> 3) & 0x70); }

#define PACK_BF16X2(res, lo, hi) \
    asm("cvt.rn.satfinite.bf16x2.f32 %0, %1, %2;" : "=r"(res) : "f"(hi), "f"(lo))

__device__ __forceinline__ void sts64(uint32_t a, uint32_t x, uint32_t y) {
    asm volatile("st.shared.v2.b32 [%0], {%1,%2};" :: "r"(a), "r"(x), "r"(y) : "memory");
}
__device__ __forceinline__ void sts128(uint32_t a, uint4 v) {
    asm volatile("st.shared.v4.b32 [%0], {%1,%2,%3,%4};" :: "r"(a), "r"(v.x), "r"(v.y), "r"(v.z), "r"(v.w) : "memory");
}
__device__ __forceinline__ void ldsm_x4(uint32_t r[4], uint32_t addr) {
    asm volatile("ldmatrix.sync.aligned.m8n8.x4.shared.b16 {%0,%1,%2,%3}, [%4];"
        : "=r"(r[0]), "=r"(r[1]), "=r"(r[2]), "=r"(r[3]) : "r"(addr));
}
__device__ __forceinline__ void mma16816(float c[4], const uint32_t a[4],
                                         uint32_t b0, uint32_t b1) {
    asm volatile("mma.sync.aligned.m16n8k16.row.col.f32.bf16.bf16.f32 "
        "{%0,%1,%2,%3}, {%4,%5,%6,%7}, {%8,%9}, {%0,%1,%2,%3};"
        : "+f"(c[0]), "+f"(c[1]), "+f"(c[2]), "+f"(c[3])
        : "r"(a[0]), "r"(a[1]), "r"(a[2]), "r"(a[3]), "r"(b0), "r"(b1));
}

__device__ __forceinline__ void split2(float v, float& f0, float& f1, float& r2) {
    f0 = __bfloat162float(__float2bfloat16_rn(v));
    float r1 = v - f0;                              // exact (Sterbenz)
    f1 = __bfloat162float(__float2bfloat16_rn(r1));
    r2 = r1 - f1;                                   // exact; rounded to bf16 at pack
}

// ---------------- W pre-split kernel ----------------
__global__ void wsplit_kernel(const float* __restrict__ W) {
    const int t = blockIdx.x;                 // k-tile
    unsigned char* dst = g_wb + (size_t)t * B_STAGE;
    for (int item = threadIdx.x; item < NEXP * 16; item += blockDim.x) {
        const int e  = item >> 4;             // expert row
        const int kq = (item & 15) * 4;       // k within tile
        float4 w = *(const float4*)(W + (size_t)e * HIDDEN + t * TK + kq);
        float v[4] = {w.x, w.y, w.z, w.w};
        float f0[4], f1[4], f2[4];
#pragma unroll
        for (int i = 0; i < 4; i++) split2(v[i], f0[i], f1[i], f2[i]);
        uint32_t u0a, u0b, u1a, u1b, u2a, u2b;
        PACK_BF16X2(u0a, f0[0], f0[1]); PACK_BF16X2(u0b, f0[2], f0[3]);
        PACK_BF16X2(u1a, f1[0], f1[1]); PACK_BF16X2(u1b, f1[2], f1[3]);
        PACK_BF16X2(u2a, f2[0], f2[1]); PACK_BF16X2(u2b, f2[2], f2[3]);
        const uint32_t off = sw128((uint32_t)(e * 128 + kq * 2));
        *(uint2*)(dst + 0 * B_TERM_BYTES + off) = make_uint2(u0a, u0b);
        *(uint2*)(dst + 1 * B_TERM_BYTES + off) = make_uint2(u1a, u1b);
        *(uint2*)(dst + 2 * B_TERM_BYTES + off) = make_uint2(u2a, u2b);
    }
}

// MMA over one smem stage. Main product (a0,b0) -> accM (drained per tile);
// corrections (a0,b1)(a0,b2)(a1,b0)(a1,b1)(a2,b0) -> accC (small magnitude).
__device__ __forceinline__ void mma_stage(
    uint32_t Ab, uint32_t Bb, float accM[2][2][4], float accC[2][2][4],
    uint32_t arow0, uint32_t arow1, uint32_t brow,
    uint32_t colb, uint32_t swz)
{
#pragma unroll
    for (int k16 = 0; k16 < 4; k16++) {
        const uint32_t coff = (colb + 32u * k16) ^ swz;
        uint32_t Bf[3][4];
#pragma unroll
        for (int tb = 0; tb < 3; tb++)
            ldsm_x4(Bf[tb], Bb + tb * B_TERM_BYTES + brow + coff);

        // ta = 0: main product to accM, (0,1) and (0,2) to accC
        {
            uint32_t Af0[4], Af1[4];
            ldsm_x4(Af0, Ab + 0 * A_TERM_BYTES + arow0 + coff);
            ldsm_x4(Af1, Ab + 0 * A_TERM_BYTES + arow1 + coff);
            mma16816(accM[0][0], Af0, Bf[0][0], Bf[0][2]);
            mma16816(accM[0][1], Af0, Bf[0][1], Bf[0][3]);
            mma16816(accM[1][0], Af1, Bf[0][0], Bf[0][2]);
            mma16816(accM[1][1], Af1, Bf[0][1], Bf[0][3]);
#pragma unroll
            for (int tb = 1; tb < 3; tb++) {
                mma16816(accC[0][0], Af0, Bf[tb][0], Bf[tb][2]);
                mma16816(accC[0][1], Af0, Bf[tb][1], Bf[tb][3]);
                mma16816(accC[1][0], Af1, Bf[tb][0], Bf[tb][2]);
                mma16816(accC[1][1], Af1, Bf[tb][1], Bf[tb][3]);
            }
        }
        // ta = 1: (1,0) and (1,1) to accC
        {
            uint32_t Af0[4], Af1[4];
            ldsm_x4(Af0, Ab + 1 * A_TERM_BYTES + arow0 + coff);
            ldsm_x4(Af1, Ab + 1 * A_TERM_BYTES + arow1 + coff);
#pragma unroll
            for (int tb = 0; tb < 2; tb++) {
                mma16816(accC[0][0], Af0, Bf[tb][0], Bf[tb][2]);
                mma16816(accC[0][1], Af0, Bf[tb][1], Bf[tb][3]);
                mma16816(accC[1][0], Af1, Bf[tb][0], Bf[tb][2]);
                mma16816(accC[1][1], Af1, Bf[tb][1], Bf[tb][3]);
            }
        }
        // ta = 2: (2,0) to accC
        {
            uint32_t Af0[4], Af1[4];
            ldsm_x4(Af0, Ab + 2 * A_TERM_BYTES + arow0 + coff);
            ldsm_x4(Af1, Ab + 2 * A_TERM_BYTES + arow1 + coff);
            mma16816(accC[0][0], Af0, Bf[0][0], Bf[0][2]);
            mma16816(accC[0][1], Af0, Bf[0][1], Bf[0][3]);
            mma16816(accC[1][0], Af1, Bf[0][0], Bf[0][2]);
            mma16816(accC[1][1], Af1, Bf[0][1], Bf[0][3]);
        }
    }
}

#define DRAIN_M()                                              \
    do {                                                       \
        _Pragma("unroll")                                      \
        for (int _i = 0; _i < 2; _i++)                         \
        _Pragma("unroll")                                      \
        for (int _j = 0; _j < 2; _j++)                         \
        _Pragma("unroll")                                      \
        for (int _q = 0; _q < 4; _q++) {                       \
            sum[_i][_j][_q] += accM[_i][_j][_q];               \
            accM[_i][_j][_q] = 0.0f;                           \
        }                                                      \
    } while (0)

// ---------------- main kernel ----------------
__global__ __launch_bounds__(NTH, 1) void router_kernel(
    const float* __restrict__ x,
    const float* __restrict__ b,
    float* __restrict__ out)
{
    extern __shared__ __align__(16) char dsmem[];
    float* biasS = (float*)dsmem;                 // [64]
    float* Cs    = (float*)(dsmem + 1024);        // epilogue: [128][CRS]
    const uint32_t TBu = smem_u32(dsmem + 1024);  // stage 0 base (smem u32)

    const int tid = threadIdx.x;
    const int wid = tid >> 5;
    const int lid = tid & 31;
    const int block_m = blockIdx.x * BM;

    // warp grid: 4 (M) x 4 (N)
    const int wm = (wid & 3) * 32;
    const int wn = (wid >> 2) * 16;

    // ldmatrix lane addressing (pre-swizzle components)
    const uint32_t lrow = (lid & 7) + ((lid >> 3) & 1) * 8;  // 0..15
    const uint32_t swz  = (lrow & 7) << 4;
    const uint32_t colb = (lid >> 4) * 16;
    const uint32_t arow0 = (wm + lrow) * 128;
    const uint32_t arow1 = (wm + 16 + lrow) * 128;
    const uint32_t brow  = (wn + lrow) * 128;

    // ---- global load mapping for A conversion
    const int r  = tid >> 2;          // token row 0..127
    const int kq = (tid & 3) * 16;    // k base within tile
    const float* xrow = x + (size_t)(block_m + r) * HIDDEN + kq;

    float accM[2][2][4], accC[2][2][4], sum[2][2][4];
#pragma unroll
    for (int i = 0; i < 2; i++)
#pragma unroll
        for (int j = 0; j < 2; j++)
#pragma unroll
            for (int q = 0; q < 4; q++) {
                accM[i][j][q] = 0.0f; accC[i][j][q] = 0.0f; sum[i][j][q] = 0.0f;
            }

    // prefetch tile 0
    float4 ax[4]; uint4 bw[3];
#pragma unroll
    for (int j = 0; j < 4; j++) ax[j] = *(const float4*)(xrow + j * 4);
    {
        const uint4* wb = (const uint4*)g_wb;
#pragma unroll
        for (int j = 0; j < 3; j++) bw[j] = wb[tid + j * NTH];
    }
    if (tid < NEXP) biasS[tid] = b[tid];

    const uint32_t stage[2] = {TBu, TBu + STAGE_BYTES};

    for (int t = 0; t < NKT; ++t) {
        const uint32_t Abase = stage[t & 1];
        const uint32_t Bbase = Abase + A_STAGE;

        // convert + store A (3 bf16 terms, SW128)
#pragma unroll
        for (int j = 0; j < 4; j++) {
            float v[4] = {ax[j].x, ax[j].y, ax[j].z, ax[j].w};
            float f0[4], f1[4], f2[4];
#pragma unroll
            for (int i = 0; i < 4; i++) split2(v[i], f0[i], f1[i], f2[i]);
            uint32_t u0a, u0b, u1a, u1b, u2a, u2b;
            PACK_BF16X2(u0a, f0[0], f0[1]); PACK_BF16X2(u0b, f0[2], f0[3]);
            PACK_BF16X2(u1a, f1[0], f1[1]); PACK_BF16X2(u1b, f1[2], f1[3]);
            PACK_BF16X2(u2a, f2[0], f2[1]); PACK_BF16X2(u2b, f2[2], f2[3]);
            const uint32_t off = sw128((uint32_t)(r * 128 + kq * 2 + j * 8));
            sts64(Abase + 0 * A_TERM_BYTES + off, u0a, u0b);
            sts64(Abase + 1 * A_TERM_BYTES + off, u1a, u1b);
            sts64(Abase + 2 * A_TERM_BYTES + off, u2a, u2b);
        }
        // store B (straight copy, pre-swizzled)
#pragma unroll
        for (int j = 0; j < 3; j++) sts128(Bbase + (tid + j * NTH) * 16, bw[j]);

        // prefetch next tile
        if (t + 1 < NKT) {
            const float* xn = xrow + (size_t)(t + 1) * TK;
#pragma unroll
            for (int j = 0; j < 4; j++) ax[j] = *(const float4*)(xn + j * 4);
            const uint4* wb = (const uint4*)(g_wb + (size_t)(t + 1) * B_STAGE);
#pragma unroll
            for (int j = 0; j < 3; j++) bw[j] = wb[tid + j * NTH];
        }

        // MMA over the PREVIOUS stage (written last iter, synced), then drain
        if (t > 0) {
            mma_stage(stage[(t - 1) & 1], stage[(t - 1) & 1] + A_STAGE,
                      accM, accC, arow0, arow1, brow, colb, swz);
            DRAIN_M();
        }
        __syncthreads();
    }
    // final stage
    mma_stage(stage[(NKT - 1) & 1], stage[(NKT - 1) & 1] + A_STAGE,
              accM, accC, arow0, arow1, brow, colb, swz);
    DRAIN_M();

    // ---- dump C = sum + corrections to smem (stage 0 region is dead now)
#pragma unroll
    for (int im = 0; im < 2; im++)
#pragma unroll
        for (int in = 0; in < 2; in++) {
            const int r0 = wm + im * 16 + (lid >> 2);
            const int c0 = wn + in * 8 + (lid & 3) * 2;
            *(float2*)&Cs[r0 * CRS + c0] =
                make_float2(sum[im][in][0] + accC[im][in][0],
                            sum[im][in][1] + accC[im][in][1]);
            *(float2*)&Cs[(r0 + 8) * CRS + c0] =
                make_float2(sum[im][in][2] + accC[im][in][2],
                            sum[im][in][3] + accC[im][in][3]);
        }
    __syncthreads();

    if (tid < BM) {
        const int m  = tid;
        const int gm = block_m + m;
        float v[NEXP];
#pragma unroll
        for (int e = 0; e < NEXP; e++) v[e] = Cs[m * CRS + e] + biasS[e];

        float* outR    = out;
        float* outWt   = out + (size_t)N_TOKENS * NEXP;
        float* outIdx  = outWt + (size_t)N_TOKENS * TOPK;
        float* outMask = outIdx + (size_t)N_TOKENS * TOPK;

        float* dst = outR + (size_t)gm * NEXP;
#pragma unroll
        for (int e = 0; e < NEXP; e += 4)
            *(float4*)(dst + e) = make_float4(v[e], v[e + 1], v[e + 2], v[e + 3]);

        // top-8, strict > (first index on ties, matching jax top_k)
        unsigned long long used = 0ull;
        float vals[TOPK]; int idxs[TOPK];
#pragma unroll
        for (int k = 0; k < TOPK; k++) {
            float best = -INFINITY; int bi = 0;
#pragma unroll
            for (int e = 0; e < NEXP; e++) {
                const bool free_e = !((used >> e) & 1ull);
                if (free_e && v[e] > best) { best = v[e]; bi = e; }
            }
            used |= 1ull << bi;
            vals[k] = best; idxs[k] = bi;
        }
        const float mx = vals[0];
        float ex[TOPK], s = 0.0f;
#pragma unroll
        for (int k = 0; k < TOPK; k++) { ex[k] = expf(vals[k] - mx); s += ex[k]; }
        const float inv = 1.0f / s;

        *(float4*)(outWt + (size_t)gm * TOPK) =
            make_float4(ex[0] * inv, ex[1] * inv, ex[2] * inv, ex[3] * inv);
        *(float4*)(outWt + (size_t)gm * TOPK + 4) =
            make_float4(ex[4] * inv, ex[5] * inv, ex[6] * inv, ex[7] * inv);
        *(float4*)(outIdx + (size_t)gm * TOPK) =
            make_float4((float)idxs[0], (float)idxs[1], (float)idxs[2], (float)idxs[3]);
        *(float4*)(outIdx + (size_t)gm * TOPK + 4) =
            make_float4((float)idxs[4], (float)idxs[5], (float)idxs[6], (float)idxs[7]);
#pragma unroll
        for (int k = 0; k < TOPK; k++)
            outMask[(size_t)(idxs[k] * TOPK + k) * N_TOKENS + gm] = 1.0f;
    }
}

extern "C" void kernel_launch(void* const* d_in, const int* in_sizes, int n_in,
                              void* d_out, int out_size)
{
    const float* x = (const float*)d_in[0];
    const float* W = (const float*)d_in[1];
    const float* b = (const float*)d_in[2];
    float* out = (float*)d_out;

    // zero the expert_mask region (rest of out fully overwritten)
    float* mask = out + (size_t)N_TOKENS * NEXP + 2 * (size_t)N_TOKENS * TOPK;
    cudaMemsetAsync(mask, 0, (size_t)NEXP * TOPK * N_TOKENS * sizeof(float), 0);

    wsplit_kernel<<<NKT, 256>>>(W);

    cudaFuncSetAttribute(router_kernel,
                         cudaFuncAttributeMaxDynamicSharedMemorySize, SMEM_BYTES);
    router_kernel<<<N_TOKENS / BM, NTH, SMEM_BYTES>>>(x, b, out);
}